// round 1
// baseline (speedup 1.0000x reference)
#include <cuda_runtime.h>

typedef unsigned long long ull;

static const int MD  = 100;     // nodes
static const int HD  = 512;     // hidden
static const int NP  = MD*MD;   // pairs
static const int WPN = 51200;   // HD*MD

// ---------------- device scratch (no runtime allocation allowed) ----------------
__device__ float g_child0[MD*HD];
__device__ float g_child1[MD*HD];
__device__ float g_child2[MD*HD];
__device__ float g_A[MD*HD];
__device__ float g_B[MD*HD];
__device__ float g_Ai[MD*HD];
__device__ float g_Bj[MD*HD];
__device__ float g_h[MD*HD];
__device__ float g_hcat[MD*3*HD];
__device__ float g_EL[NP*HD];          // edge latents (only ok-pairs written)
__device__ float g_Ce0[NP*HD];         // edge_latents @ We (iter 0)
__device__ float g_Ce1[NP*HD];         // edge_latents @ We (iter 1)
__device__ float g_gpart[4*WPN];       // split-k partials for parent GEMV
__device__ float g_part[8*MD*HD];      // split-k partials for skinny GEMMs
__device__ int   g_nodeok[MD];
__device__ int   g_pairlist[NP];
__device__ int   g_paircnt;

__device__ __forceinline__ ull ffma2(ull a, ull b, ull c){
    ull d;
    asm("fma.rn.f32x2 %0, %1, %2, %3;" : "=l"(d) : "l"(a), "l"(b), "l"(c));
    return d;
}
__device__ __forceinline__ ull dup2(float v){
    unsigned u = __float_as_uint(v);
    return ((ull)u << 32) | (ull)u;
}

__device__ __forceinline__ float* sel_buf(int code, float* p){
    switch (code){
        case 0: return g_A;      case 1: return g_B;
        case 2: return g_Ai;     case 3: return g_Bj;
        case 4: return g_h;      case 5: return g_child0;
        case 6: return g_child1; case 7: return g_child2;
        case 8: return g_hcat;
        default: return p;
    }
}

// ---------------- kernels ----------------
__global__ void k_init(){ g_paircnt = 0; }

// child = relu(pf @ W_parent + b): split-K partials. grid (200, 4), 256 thr.
__global__ void k_gemv_part(const float* __restrict__ pf, const float* __restrict__ Wp){
    __shared__ float pfs[128];
    const int z = blockIdx.y;
    const int c = blockIdx.x*256 + threadIdx.x;
    if (threadIdx.x < 128) pfs[threadIdx.x] = pf[z*128 + threadIdx.x];
    __syncthreads();
    const float* w = Wp + (long long)(z*128)*WPN + c;
    float a0=0.f, a1=0.f, a2=0.f, a3=0.f;
    #pragma unroll 8
    for (int k=0; k<128; k+=4){
        a0 += pfs[k  ] * w[(long long)(k  )*WPN];
        a1 += pfs[k+1] * w[(long long)(k+1)*WPN];
        a2 += pfs[k+2] * w[(long long)(k+2)*WPN];
        a3 += pfs[k+3] * w[(long long)(k+3)*WPN];
    }
    g_gpart[z*WPN + c] = (a0+a1)+(a2+a3);
}

__global__ void k_gemv_fin(const float* __restrict__ bp){
    int c = blockIdx.x*256 + threadIdx.x;
    float s = g_gpart[c] + g_gpart[WPN+c] + g_gpart[2*WPN+c] + g_gpart[3*WPN+c] + bp[c];
    g_child0[c] = fmaxf(s, 0.f);
}

// exists_logits + node_ok. grid 100, 128 thr.
__global__ void k_exists(const float* __restrict__ Wx, const float* __restrict__ bx,
                         float* __restrict__ out_exists){
    __shared__ float red[128];
    int m = blockIdx.x, t = threadIdx.x;
    float s = 0.f;
    #pragma unroll
    for (int q=0; q<4; q++) s += g_child0[m*HD + t + q*128] * Wx[t + q*128];
    red[t] = s; __syncthreads();
    for (int st=64; st>0; st>>=1){ if (t<st) red[t]+=red[t+st]; __syncthreads(); }
    if (t==0){
        float v = red[0] + bx[0];
        out_exists[m] = v;
        g_nodeok[m]   = (v > 0.f) ? 1 : 0;
    }
}

// generic split-K GEMM partial: C_part[z] = A[M,K-slice] @ B[K-slice,N]
// BM=32, BN=64, BK=16, 256 threads, 2x4 micro-tile.
__global__ void k_gemm_part(int Acode, const float* Aptr, int lda,
                            const float* __restrict__ B, int ldb,
                            int Mrows, int N, int Ksplit, int MN){
    __shared__ float As[16*33];
    __shared__ float Bs[16*68];
    const float* A = sel_buf(Acode, (float*)Aptr);
    const int n0 = blockIdx.x*64, m0 = blockIdx.y*32, z = blockIdx.z;
    const int kbase = z * Ksplit;
    const int t = threadIdx.x;
    const int tr = t >> 4, tc = t & 15;
    float acc[2][4] = {};
    for (int kt=0; kt<Ksplit; kt+=16){
        #pragma unroll
        for (int q=0; q<2; q++){
            int idx = t + q*256;
            int r = idx >> 4, kk = idx & 15;
            float v = 0.f;
            int gm = m0 + r;
            if (gm < Mrows) v = A[gm*lda + kbase + kt + kk];
            As[kk*33 + r] = v;
        }
        #pragma unroll
        for (int q=0; q<4; q++){
            int idx = t + q*256;
            int bk = idx >> 6, bn = idx & 63;
            float v = 0.f;
            int gn = n0 + bn;
            if (gn < N) v = B[(kbase + kt + bk)*ldb + gn];
            Bs[bk*68 + bn] = v;
        }
        __syncthreads();
        #pragma unroll
        for (int k=0; k<16; k++){
            float a0 = As[k*33 + tr], a1 = As[k*33 + tr + 16];
            float4 b = *(const float4*)&Bs[k*68 + tc*4];
            acc[0][0] += a0*b.x; acc[0][1] += a0*b.y; acc[0][2] += a0*b.z; acc[0][3] += a0*b.w;
            acc[1][0] += a1*b.x; acc[1][1] += a1*b.y; acc[1][2] += a1*b.z; acc[1][3] += a1*b.w;
        }
        __syncthreads();
    }
    #pragma unroll
    for (int rr=0; rr<2; rr++){
        int gm = m0 + tr + rr*16;
        if (gm < Mrows){
            #pragma unroll
            for (int cc=0; cc<4; cc++){
                int gn = n0 + tc*4 + cc;
                if (gn < N) g_part[z*MN + gm*N + gn] = acc[rr][cc];
            }
        }
    }
}

__global__ void k_reduce(int dstcode, float* dstptr, int MN, int N,
                         const float* __restrict__ bias, int act, int S){
    float* dst = sel_buf(dstcode, dstptr);
    int i = blockIdx.x*256 + threadIdx.x;
    if (i >= MN) return;
    float s = 0.f;
    for (int z=0; z<S; z++) s += g_part[z*MN + i];
    if (bias) s += bias[i % N];
    if (act) s = fmaxf(s, 0.f);
    dst[i] = s;
}

// edge latents + edge_exists_logits. grid (100,100), 256 thr.
__global__ void k_el(const float* __restrict__ bel, const float* __restrict__ Wee,
                     const float* __restrict__ bee, float* __restrict__ out_lg){
    __shared__ float4 red[256];
    const int i = blockIdx.x, j = blockIdx.y, t = threadIdx.x;
    float v0 = fmaxf(g_A[i*HD + t      ] + g_B[j*HD + t      ] + bel[t      ], 0.f);
    float v1 = fmaxf(g_A[i*HD + t + 256] + g_B[j*HD + t + 256] + bel[t + 256], 0.f);
    if (g_nodeok[i] && g_nodeok[j]){
        int pb = (i*MD + j)*HD;
        g_EL[pb + t] = v0; g_EL[pb + t + 256] = v1;
    }
    float p0 = v0*Wee[0*HD+t] + v1*Wee[0*HD+t+256];
    float p1 = v0*Wee[1*HD+t] + v1*Wee[1*HD+t+256];
    float p2 = v0*Wee[2*HD+t] + v1*Wee[2*HD+t+256];
    float p3 = v0*Wee[3*HD+t] + v1*Wee[3*HD+t+256];
    red[t] = make_float4(p0,p1,p2,p3);
    __syncthreads();
    for (int s=128; s>0; s>>=1){
        if (t < s){
            float4 o = red[t+s];
            red[t].x += o.x; red[t].y += o.y; red[t].z += o.z; red[t].w += o.w;
        }
        __syncthreads();
    }
    if (t == 0){
        int base = (i*MD + j)*4;
        out_lg[base+0] = red[0].x + bee[0];
        out_lg[base+1] = red[0].y + bee[1];
        out_lg[base+2] = red[0].z + bee[2];
        out_lg[base+3] = red[0].w + bee[3];
    }
}

// compact active pairs. grid 40, 256 thr.
__global__ void k_pairs(const float* __restrict__ lg){
    int p = blockIdx.x*256 + threadIdx.x;
    if (p >= NP) return;
    int i = p / MD, j = p % MD;
    if (g_nodeok[i] && g_nodeok[j]){
        const float* l = lg + p*4;
        if (l[0] > 0.f || l[1] > 0.f || l[2] > 0.f || l[3] > 0.f){
            int pos = atomicAdd(&g_paircnt, 1);
            g_pairlist[pos] = p;
        }
    }
}

// gathered GEMM: Ce[pair] = EL[pair] @ We, f32x2 packed FFMA.
// BM=64, BN=64, BK=16, 256 threads, 4 rows x 4 cols (2 f32x2 pairs) per thread.
__global__ void k_ce(const float* __restrict__ We, int it){
    __shared__ int  pidx[64];
    __shared__ ull  As2[16*65];   // duplicated A values for packed math
    __shared__ float Bs[16*68];
    float* C = it ? g_Ce1 : g_Ce0;
    const int cnt = g_paircnt;
    const int m0 = blockIdx.y*64;
    if (m0 >= cnt) return;
    const int n0 = blockIdx.x*64;
    const int t = threadIdx.x;
    if (t < 64) pidx[t] = (m0 + t < cnt) ? g_pairlist[m0 + t] : g_pairlist[m0];
    __syncthreads();
    const int tr = t >> 4, tc4 = (t & 15)*4;
    ull acc[4][2] = {};
    for (int kt=0; kt<HD; kt+=16){
        #pragma unroll
        for (int q=0; q<4; q++){
            int idx = t + q*256;
            int r = idx >> 4, kk = idx & 15;
            float v = g_EL[pidx[r]*HD + kt + kk];
            As2[kk*65 + r] = dup2(v);
        }
        #pragma unroll
        for (int q=0; q<4; q++){
            int idx = t + q*256;
            int bk = idx >> 6, bn = idx & 63;
            Bs[bk*68 + bn] = We[(kt + bk)*HD + n0 + bn];
        }
        __syncthreads();
        #pragma unroll
        for (int k=0; k<16; k++){
            ull a0 = As2[k*65 + tr];
            ull a1 = As2[k*65 + tr + 16];
            ull a2 = As2[k*65 + tr + 32];
            ull a3 = As2[k*65 + tr + 48];
            ull b0 = *reinterpret_cast<const ull*>(&Bs[k*68 + tc4]);
            ull b1 = *reinterpret_cast<const ull*>(&Bs[k*68 + tc4 + 2]);
            acc[0][0] = ffma2(a0,b0,acc[0][0]); acc[0][1] = ffma2(a0,b1,acc[0][1]);
            acc[1][0] = ffma2(a1,b0,acc[1][0]); acc[1][1] = ffma2(a1,b1,acc[1][1]);
            acc[2][0] = ffma2(a2,b0,acc[2][0]); acc[2][1] = ffma2(a2,b1,acc[2][1]);
            acc[3][0] = ffma2(a3,b0,acc[3][0]); acc[3][1] = ffma2(a3,b1,acc[3][1]);
        }
        __syncthreads();
    }
    #pragma unroll
    for (int rr=0; rr<4; rr++){
        int rl = tr + rr*16;
        if (m0 + rl < cnt){
            float* cp = C + pidx[rl]*HD + n0 + tc4;
            cp[0] = __uint_as_float((unsigned)(acc[rr][0]      ));
            cp[1] = __uint_as_float((unsigned)(acc[rr][0] >> 32));
            cp[2] = __uint_as_float((unsigned)(acc[rr][1]      ));
            cp[3] = __uint_as_float((unsigned)(acc[rr][1] >> 32));
        }
    }
}

// message pass + scatter-sum. grid 100, 512 thr.
__global__ void k_msg(int it, const float* __restrict__ lgg,
                      const float* __restrict__ Wt, const float* __restrict__ bne){
    __shared__ float lg[400];
    __shared__ int   okj[100];
    const float* childin  = it ? g_child1 : g_child0;
    float*       childout = it ? g_child2 : g_child1;
    const float* Ce       = it ? g_Ce1    : g_Ce0;
    const int i = blockIdx.x, h = threadIdx.x;
    if (h < 400) lg[h] = lgg[i*400 + h];
    if (h >= 400 && h < 500) okj[h-400] = g_nodeok[h-400];
    __syncthreads();
    float cin = childin[i*HD + h];
    bool any = (g_paircnt > 0);
    float acc = 0.f;
    if (any && g_nodeok[i]){
        float base_i = g_Ai[i*HD + h] + bne[h];
        float wt0 = Wt[h], wt1 = Wt[HD+h], wt2 = Wt[2*HD+h], wt3 = Wt[3*HD+h];
        for (int j=0; j<MD; j++){
            if (!okj[j]) continue;
            float l0 = lg[j*4], l1 = lg[j*4+1], l2 = lg[j*4+2], l3 = lg[j*4+3];
            if (l0 <= 0.f && l1 <= 0.f && l2 <= 0.f && l3 <= 0.f) continue;
            float base = base_i + g_Bj[j*HD + h] + Ce[(i*MD + j)*HD + h];
            if (l0 > 0.f) acc += fmaxf(base + l0*wt0, 0.f);
            if (l1 > 0.f) acc += fmaxf(base + l1*wt1, 0.f);
            if (l2 > 0.f) acc += fmaxf(base + l2*wt2, 0.f);
            if (l3 > 0.f) acc += fmaxf(base + l3*wt3, 0.f);
        }
    }
    childout[i*HD + h] = any ? acc : cin;
}

__global__ void k_hcat(){
    int m = blockIdx.x, z = blockIdx.y, t = threadIdx.x;
    const float* src = (z==0) ? g_child0 : (z==1) ? g_child1 : g_child2;
    g_hcat[m*(3*HD) + z*HD + t] = src[m*HD + t];
}

// ---------------- launch ----------------
extern "C" void kernel_launch(void* const* d_in, const int* in_sizes, int n_in,
                              void* d_out, int out_size){
    const float* pf  = (const float*)d_in[0];
    const float* Wp  = (const float*)d_in[1];
    const float* bp  = (const float*)d_in[2];
    const float* Wx  = (const float*)d_in[3];
    const float* bx  = (const float*)d_in[4];
    const float* Wel = (const float*)d_in[5];
    const float* bel = (const float*)d_in[6];
    const float* Wee = (const float*)d_in[7];
    const float* bee = (const float*)d_in[8];
    const float* Wne = (const float*)d_in[9];
    const float* bne = (const float*)d_in[10];
    const float* Wc  = (const float*)d_in[11];
    const float* bc  = (const float*)d_in[12];
    const float* Ws  = (const float*)d_in[13];
    const float* bs  = (const float*)d_in[14];
    const float* Wc2 = (const float*)d_in[15];
    const float* bc2 = (const float*)d_in[16];

    float* out     = (float*)d_out;
    float* out_co  = out;            // child_out  [100,512]
    float* out_sem = out + 51200;    // sem_logits [100,57]
    float* out_ex  = out + 56900;    // exists     [100,1]
    float* out_lg  = out + 57000;    // edge_exists_logits [100,100,4]

    k_init<<<1,1>>>();
    k_gemv_part<<<dim3(200,4),256>>>(pf, Wp);
    k_gemv_fin<<<200,256>>>(bp);
    k_exists<<<100,128>>>(Wx, bx, out_ex);

    // A_el / B_el
    k_gemm_part<<<dim3(8,4,8),256>>>(5, nullptr, 512, Wel,           512, 100, 512, 64, 51200);
    k_reduce<<<200,256>>>(0, nullptr, 51200, 512, nullptr, 0, 8);
    k_gemm_part<<<dim3(8,4,8),256>>>(5, nullptr, 512, Wel + 512*512, 512, 100, 512, 64, 51200);
    k_reduce<<<200,256>>>(1, nullptr, 51200, 512, nullptr, 0, 8);

    k_el<<<dim3(100,100),256>>>(bel, Wee, bee, out_lg);
    k_pairs<<<40,256>>>(out_lg);

    // both iterations' Ce (edge latents are iteration-invariant)
    k_ce<<<dim3(8,157),256>>>(Wne + 1024*512,          0);
    k_ce<<<dim3(8,157),256>>>(Wne + (1540+1024)*512,   1);

    // iteration 0
    k_gemm_part<<<dim3(8,4,8),256>>>(5, nullptr, 512, Wne,            512, 100, 512, 64, 51200);
    k_reduce<<<200,256>>>(2, nullptr, 51200, 512, nullptr, 0, 8);
    k_gemm_part<<<dim3(8,4,8),256>>>(5, nullptr, 512, Wne + 512*512,  512, 100, 512, 64, 51200);
    k_reduce<<<200,256>>>(3, nullptr, 51200, 512, nullptr, 0, 8);
    k_msg<<<100,512>>>(0, out_lg, Wne + 1536*512, bne);

    // iteration 1
    k_gemm_part<<<dim3(8,4,8),256>>>(6, nullptr, 512, Wne + 1540*512,        512, 100, 512, 64, 51200);
    k_reduce<<<200,256>>>(2, nullptr, 51200, 512, nullptr, 0, 8);
    k_gemm_part<<<dim3(8,4,8),256>>>(6, nullptr, 512, Wne + (1540+512)*512,  512, 100, 512, 64, 51200);
    k_reduce<<<200,256>>>(3, nullptr, 51200, 512, nullptr, 0, 8);
    k_msg<<<100,512>>>(1, out_lg, Wne + (1540+1536)*512, bne + 512);

    // final heads
    k_hcat<<<dim3(100,3),512>>>();
    k_gemm_part<<<dim3(8,4,8),256>>>(8, nullptr, 1536, Wc, 512, 100, 512, 192, 51200);
    k_reduce<<<200,256>>>(4, nullptr, 51200, 512, bc, 1, 8);
    k_gemm_part<<<dim3(1,4,8),256>>>(4, nullptr, 512, Ws, 57, 100, 57, 64, 5700);
    k_reduce<<<23,256>>>(-1, out_sem, 5700, 57, bs, 0, 8);
    k_gemm_part<<<dim3(8,4,8),256>>>(4, nullptr, 512, Wc2, 512, 100, 512, 64, 51200);
    k_reduce<<<200,256>>>(-1, out_co, 51200, 512, bc2, 1, 8);
}